// round 8
// baseline (speedup 1.0000x reference)
#include <cuda_runtime.h>

// Problem constants: B=2, L=1024, M=8, N=16, C=16, H=W=64
#define BB 2
#define LL 1024
#define MM 8
#define NN 16
#define CC 16
#define HH 64
#define WW 64
#define NVOTE (MM * NN)          // 128 votes per anchor
#define NBIN  (HH * WW)          // 4096 bins
#define THREADS 256
#define NCHUNK (NBIN / 4 / THREADS)   // 4
#define TOTAL (BB * LL)          // 2048 anchors
#define GRID  512                // persistent CTAs: exactly 4 anchors each

struct alignas(16) Buf {
    short slot_of_bin[NBIN];     // 8 KB: bin -> slot id or -1 (16B aligned)
    short vote_slot[NVOTE];
    int   s_sh[MM];
    int   nslots;
    float slotw[NVOTE][CC + 1];  // padded to 17 to spread banks
};

__device__ __forceinline__ void clear_buf(Buf& bf, int tid)
{
    int* sb = reinterpret_cast<int*>(bf.slot_of_bin);
    #pragma unroll
    for (int i = tid; i < NBIN / 2; i += THREADS) sb[i] = -1;
    float* w = &bf.slotw[0][0];
    #pragma unroll
    for (int i = tid; i < NVOTE * (CC + 1); i += THREADS) w[i] = 0.0f;
    if (tid == 0) bf.nslots = 0;
}

// Phase A: one thread per vote — gather chain, bin, claim compact slot.
__device__ __forceinline__ void phaseA(Buf& bf, int bl, int tid,
                                       const int* __restrict__ vsrc,
                                       const int* __restrict__ vdst,
                                       const int* __restrict__ isrc,
                                       const int* __restrict__ idst)
{
    if (tid < NVOTE) {
        const int b = bl >> 10;        // L = 1024
        const int v = tid;
        const int m = v >> 4;          // N = 16
        const int n = v & 15;

        const int s = isrc[bl * MM + m];
        if (n == 0) bf.s_sh[m] = s;

        const int base_s = b * LL + s;
        const int dd     = idst[base_s * NN + n];
        const int base_d = b * LL + dd;

        const int by = vdst[base_d * 2]     - vsrc[base_s * 2]     + HH / 2;
        const int bx = vdst[base_d * 2 + 1] - vsrc[base_s * 2 + 1] + WW / 2;

        short sl = -1;
        if (by >= 0 && by < HH && bx >= 0 && bx < WW) {
            const int hw = by * WW + bx;
            sl = bf.slot_of_bin[hw];
            if (sl < 0) {
                const int mine = atomicAdd(&bf.nslots, 1);
                const unsigned short prev =
                    atomicCAS(reinterpret_cast<unsigned short*>(&bf.slot_of_bin[hw]),
                              (unsigned short)0xFFFFu, (unsigned short)mine);
                sl = (prev == 0xFFFFu) ? (short)mine : (short)prev;
            }
        }
        bf.vote_slot[v] = sl;
    }
}

// Phase B: accumulate weights; 16 consecutive threads share a vote
// -> coalesced 64B feats reads.
__device__ __forceinline__ void phaseB(Buf& bf, int bl, int tid,
                                       const float* __restrict__ feats)
{
    const int b = bl >> 10;
    #pragma unroll
    for (int i = tid; i < NVOTE * CC; i += THREADS) {
        const int v  = i >> 4;
        const int c  = i & 15;
        const int sl = bf.vote_slot[v];
        if (sl >= 0) {
            const int m = v >> 4;
            const int n = v & 15;
            const float w = feats[((b * LL + bf.s_sh[m]) * NN + n) * CC + c];
            atomicAdd(&bf.slotw[sl][c], w);
        }
    }
}

// Phase C (half): stream chunks [K0,K1) of the dense [C,H,W] tile.
template<int K0, int K1>
__device__ __forceinline__ void phaseC(const Buf& bf, int bl, int tid,
                                       float* __restrict__ out)
{
    float4* out4 = reinterpret_cast<float4*>(out + (size_t)bl * CC * NBIN);
    const short4* sb4 = reinterpret_cast<const short4*>(bf.slot_of_bin);

    #pragma unroll
    for (int k = K0; k < K1; k++) {
        const int idx4 = k * THREADS + tid;
        const short4 s4 = sb4[idx4];
        #pragma unroll
        for (int c = 0; c < CC; c++) {
            float4 val;
            val.x = (s4.x >= 0) ? bf.slotw[s4.x][c] : 0.0f;
            val.y = (s4.y >= 0) ? bf.slotw[s4.y][c] : 0.0f;
            val.z = (s4.z >= 0) ? bf.slotw[s4.z][c] : 0.0f;
            val.w = (s4.w >= 0) ? bf.slotw[s4.w][c] : 0.0f;
            __stcs(&out4[c * (NBIN / 4) + idx4], val);
        }
    }
}

__global__ __launch_bounds__(THREADS, 4)
void ht_vote_kernel(const float* __restrict__ feats,   // [B,L,N,C]
                    const int*   __restrict__ vsrc,    // [B,L,2] (y,x)
                    const int*   __restrict__ vdst,    // [B,L,2]
                    const int*   __restrict__ isrc,    // [B,L,M]
                    const int*   __restrict__ idst,    // [B,L,N]
                    float*       __restrict__ out)     // [B,L,C,H,W]
{
    __shared__ Buf buf[2];
    const int tid = threadIdx.x;

    int bl = blockIdx.x;                  // anchors bl, bl+GRID, ...

    // ---- prologue: fill buf[0] for the first anchor ----
    clear_buf(buf[0], tid);
    clear_buf(buf[1], tid);
    __syncthreads();
    phaseA(buf[0], bl, tid, vsrc, vdst, isrc, idst);
    __syncthreads();
    phaseB(buf[0], bl, tid, feats);
    __syncthreads();

    int cur = 0;
    while (bl < TOTAL) {
        const int  nbl  = bl + GRID;
        const bool more = (nbl < TOTAL);

        // Overlap: next anchor's gather/claim rides in the issue slots
        // between the current anchor's streaming stores.
        if (more) phaseA(buf[cur ^ 1], nbl, tid, vsrc, vdst, isrc, idst);
        phaseC<0, NCHUNK / 2>(buf[cur], bl, tid, out);
        __syncthreads();                      // phase A of next visible

        if (more) phaseB(buf[cur ^ 1], nbl, tid, feats);
        phaseC<NCHUNK / 2, NCHUNK>(buf[cur], bl, tid, out);
        __syncthreads();                      // buf[cur] no longer read

        if (more) clear_buf(buf[cur], tid);   // ready for anchor bl+2*GRID
        __syncthreads();

        cur ^= 1;
        bl = nbl;
    }
}

extern "C" void kernel_launch(void* const* d_in, const int* in_sizes, int n_in,
                              void* d_out, int out_size)
{
    const float* feats = (const float*)d_in[0];   // feats_src_dst [B,L,N,C]
    const int*   vsrc  = (const int*)  d_in[1];   // voxels_src    [B,L,2]
    const int*   vdst  = (const int*)  d_in[2];   // voxels_dst    [B,L,2]
    const int*   isrc  = (const int*)  d_in[3];   // idxs_src      [B,L,M]
    const int*   idst  = (const int*)  d_in[4];   // idxs_dst      [B,L,N]
    float*       out   = (float*)d_out;           // [B,L,C,H,W]

    ht_vote_kernel<<<GRID, THREADS>>>(feats, vsrc, vdst, isrc, idst, out);
}